// round 12
// baseline (speedup 1.0000x reference)
#include <cuda_runtime.h>
#include <cuda_fp16.h>
#include <cuda.h>
#include <cstdint>

#define BB 8
#define NN 4096
#define FI 128
#define FO 64
#define BI 128
#define BJ 64
#define NT (NN / BJ)
#define PPITCH 72

// k_attn shared memory layout (dynamic):
//   adj: 2 stages x 32768B (128 rows x 256B; TMA box 64x128 ints)
//   h:   2 stages x 8192B  (SW128-swizzled tiles, 1D bulk)
//   p:   1 buffer 18432B (128 x 72 halves)
//   rs:  128 floats; 2 mbarriers
#define ASTAGE_B 32768
#define HSTAGE_B 8192
#define ADJ_OFF  0
#define H_OFF    (2 * ASTAGE_B)             // 65536
#define P_OFF    (H_OFF + 2 * HSTAGE_B)     // 81920
#define RS_OFF   (P_OFF + BI * PPITCH * 2)  // 100352
#define BAR_OFF  (RS_OFF + BI * 4)          // 100864
#define ATTN_SMEM (BAR_OFF + 16)            // 100880

// Scratch (static __device__ — no allocation allowed)
// h_fp16: per batch, tile-major; within 64-row tile: row lr, byte col cb at
// lr*128 + (cb ^ ((lr&7)<<4))  (SW128 pre-swizzle).
__device__ __align__(1024) __half h_fp16[(size_t)BB * NN * FO];   // 4 MB
__device__ float  s1_g[BB * NN];
__device__ float  s2_g[BB * NN];
__device__ float2 pq1_g[BB * NN];                 // {P1, Q1} per (b,i)
__device__ float2 pq2_g[BB * NN];                 // {P2, Q2} per (b,j)

// ---------------------------------------------------------------------------
// Kernel A1: h = inp @ W (fp32, fp16 store swizzled), s1 = h@a1, s2 = h@a2
// ---------------------------------------------------------------------------
#define KH_IPITCH 132
#define KH_SMEM ((FI * FO + 64 * KH_IPITCH + 2 * FO) * 4)

__global__ __launch_bounds__(256) void k_h(const float* __restrict__ inp,
                                           const float* __restrict__ W,
                                           const float* __restrict__ a)
{
    extern __shared__ float sm_f[];
    float* W_sm   = sm_f;                       // 128*64
    float* inp_sm = sm_f + FI * FO;             // 64*132
    float* a_sm   = inp_sm + 64 * KH_IPITCH;    // 128

    const int tid = threadIdx.x;
    const int blk = blockIdx.x;                 // 0 .. BB*NN/64-1
    const int b   = blk / (NN / 64);
    const int i0  = (blk % (NN / 64)) * 64;

#pragma unroll
    for (int k = 0; k < 8; k++)
        ((float4*)W_sm)[tid + k * 256] = ((const float4*)W)[tid + k * 256];
    if (tid < 2 * FO) a_sm[tid] = a[tid];
    const float* inp_b = inp + ((size_t)b * NN + i0) * FI;
#pragma unroll
    for (int k = 0; k < 8; k++) {
        int c = tid + k * 256;
        int row = c >> 5, col = c & 31;
        *(float4*)(inp_sm + row * KH_IPITCH + col * 4) = ((const float4*)inp_b)[c];
    }
    __syncthreads();

    const int ox = tid & 15;
    const int rg = tid >> 4;
    const float4* Wv = (const float4*)W_sm;

    float4 acc[4];
#pragma unroll
    for (int k = 0; k < 4; k++) acc[k] = make_float4(0.f, 0.f, 0.f, 0.f);

#pragma unroll 4
    for (int f = 0; f < FI; f++) {
        float4 w = Wv[f * 16 + ox];
#pragma unroll
        for (int k = 0; k < 4; k++) {
            float x = inp_sm[(rg + 16 * k) * KH_IPITCH + f];
            acc[k].x += x * w.x; acc[k].y += x * w.y;
            acc[k].z += x * w.z; acc[k].w += x * w.w;
        }
    }

    char* tile_base = (char*)h_fp16 + ((size_t)b * NN + i0) * (FO * 2);

    const int o4 = ox * 4;
#pragma unroll
    for (int k = 0; k < 4; k++) {
        float s1p = acc[k].x * a_sm[o4] + acc[k].y * a_sm[o4 + 1]
                  + acc[k].z * a_sm[o4 + 2] + acc[k].w * a_sm[o4 + 3];
        float s2p = acc[k].x * a_sm[FO + o4] + acc[k].y * a_sm[FO + o4 + 1]
                  + acc[k].z * a_sm[FO + o4 + 2] + acc[k].w * a_sm[FO + o4 + 3];
#pragma unroll
        for (int m = 8; m >= 1; m >>= 1) {
            s1p += __shfl_xor_sync(0xffffffffu, s1p, m);
            s2p += __shfl_xor_sync(0xffffffffu, s2p, m);
        }
        const int lr = rg + 16 * k;
        const int grow = b * NN + i0 + lr;
        if (ox == 0) { s1_g[grow] = s1p; s2_g[grow] = s2p; }

        __half2 h01 = __floats2half2_rn(acc[k].x, acc[k].y);
        __half2 h23 = __floats2half2_rn(acc[k].z, acc[k].w);
        uint2 pk;
        pk.x = reinterpret_cast<uint32_t&>(h01);
        pk.y = reinterpret_cast<uint32_t&>(h23);
        uint32_t swz = (uint32_t)(lr * 128) + (((uint32_t)(ox * 8)) ^ (((uint32_t)lr & 7u) << 4));
        *reinterpret_cast<uint2*>(tile_base + swz) = pk;
    }
}

// ---------------------------------------------------------------------------
// Kernel A2: exp factor tables.  exp(lrelu(s1+s2) - M/L) = max(P1*P2, Q1*Q2)
// ---------------------------------------------------------------------------
__global__ void k_pq()
{
    const int b = blockIdx.x;
    const int tid = threadIdx.x;      // 512 threads
    __shared__ float red[16];

    const float* s2b = s2_g + b * NN;
    float mx = -1e30f;
    for (int j = tid; j < NN; j += 512) mx = fmaxf(mx, s2b[j]);
#pragma unroll
    for (int m = 16; m >= 1; m >>= 1)
        mx = fmaxf(mx, __shfl_xor_sync(0xffffffffu, mx, m));
    if ((tid & 31) == 0) red[tid >> 5] = mx;
    __syncthreads();
    if (tid == 0) {
        float v = red[0];
        for (int k = 1; k < 16; k++) v = fmaxf(v, red[k]);
        red[0] = v;
    }
    __syncthreads();

    const float L = 1.4426950408889634f;
    const float s2maxL = red[0] * L;
    for (int j = tid; j < NN; j += 512) {
        float sL = s2b[j] * L;
        pq2_g[b * NN + j] = make_float2(exp2f(sL), exp2f(0.2f * sL));
        float s1L = s1_g[b * NN + j] * L;
        float t = s1L + s2maxL;
        float M = fmaxf(t, 0.2f * t);
        pq1_g[b * NN + j] = make_float2(exp2f(s1L - M), exp2f(0.2f * s1L - M));
    }
}

// ---------------------------------------------------------------------------
// PTX helpers
// ---------------------------------------------------------------------------
__device__ __forceinline__ void ldsm4(uint32_t& r0, uint32_t& r1, uint32_t& r2, uint32_t& r3, uint32_t addr)
{
    asm volatile("ldmatrix.sync.aligned.m8n8.x4.shared.b16 {%0,%1,%2,%3}, [%4];"
                 : "=r"(r0), "=r"(r1), "=r"(r2), "=r"(r3) : "r"(addr));
}
__device__ __forceinline__ void ldsm4t(uint32_t& r0, uint32_t& r1, uint32_t& r2, uint32_t& r3, uint32_t addr)
{
    asm volatile("ldmatrix.sync.aligned.m8n8.x4.trans.shared.b16 {%0,%1,%2,%3}, [%4];"
                 : "=r"(r0), "=r"(r1), "=r"(r2), "=r"(r3) : "r"(addr));
}
__device__ __forceinline__ void mma16816(float* d, uint32_t a0, uint32_t a1, uint32_t a2, uint32_t a3,
                                         uint32_t b0, uint32_t b1)
{
    asm volatile("mma.sync.aligned.m16n8k16.row.col.f32.f16.f16.f32 "
                 "{%0,%1,%2,%3}, {%4,%5,%6,%7}, {%8,%9}, {%0,%1,%2,%3};"
                 : "+f"(d[0]), "+f"(d[1]), "+f"(d[2]), "+f"(d[3])
                 : "r"(a0), "r"(a1), "r"(a2), "r"(a3), "r"(b0), "r"(b1));
}
__device__ __forceinline__ void bulk_g2s(uint32_t dst, const void* src, uint32_t bytes, uint32_t bar)
{
    asm volatile("cp.async.bulk.shared::cluster.global.mbarrier::complete_tx::bytes "
                 "[%0], [%1], %2, [%3];"
                 :: "r"(dst), "l"(src), "r"(bytes), "r"(bar) : "memory");
}
__device__ __forceinline__ void tma3d(uint32_t dst, const CUtensorMap* map,
                                      int cx_, int cy_, int cz_, uint32_t bar)
{
    asm volatile("cp.async.bulk.tensor.3d.shared::cta.global.tile.mbarrier::complete_tx::bytes "
                 "[%0], [%1, {%2, %3, %4}], [%5];"
                 :: "r"(dst), "l"(map), "r"(cx_), "r"(cy_), "r"(cz_), "r"(bar) : "memory");
}
#define MBINIT(addr, cnt) \
    asm volatile("mbarrier.init.shared.b64 [%0], %1;" :: "r"(addr), "r"(cnt) : "memory")
#define MBEXP(addr, tx) \
    asm volatile("mbarrier.arrive.expect_tx.shared.b64 _, [%0], %1;" :: "r"(addr), "r"((uint32_t)(tx)) : "memory")
#define MBWAIT(addr, ph) do {                                                       \
    uint32_t _m = (addr); uint32_t _p = (ph); uint32_t _ok;                         \
    asm volatile("{\n\t.reg .pred p;\n\t"                                           \
        "mbarrier.try_wait.parity.acquire.cta.shared::cta.b64 p, [%1], %2;\n\t"     \
        "selp.b32 %0, 1, 0, p;\n\t}" : "=r"(_ok) : "r"(_m), "r"(_p) : "memory");    \
    if (!_ok) {                                                                     \
        asm volatile("{\n\t.reg .pred P1;\n\t"                                      \
            "WL_%=:\n\t"                                                            \
            "mbarrier.try_wait.parity.acquire.cta.shared::cta.b64 P1, [%0], %1, 0x989680;\n\t" \
            "@P1 bra.uni WD_%=;\n\t"                                                \
            "bra.uni WL_%=;\n\t"                                                    \
            "WD_%=:\n\t}" :: "r"(_m), "r"(_p) : "memory");                          \
    }                                                                               \
} while (0)

// ---------------------------------------------------------------------------
// Kernel B: fused mask + softmax(no-rescale) + PV matmul + elu.
// 256 CTAs x 256 threads (8 warps), 2 CTAs/SM — SINGLE WAVE.
// Warp (rg=warp&3, ch=warp>>2): rows rg*32..+31, cols ch*32..+31.
// TRUE distance-1 pipeline: issue(t+1) BEFORE waiting for tile t, so two
// tiles are always in flight per CTA. Stage (t+1)&1 reuse is safe because
// MMA(t-1) finished before the end-of-iteration sync of iter t-1.
// ---------------------------------------------------------------------------
__global__ __launch_bounds__(256, 2) void k_attn(
    const __grid_constant__ CUtensorMap tm_adj,
    float* __restrict__ out)
{
    extern __shared__ __align__(1024) unsigned char smem[];
    const uint32_t sb = (uint32_t)__cvta_generic_to_shared(smem);
    __half* p_sm = (__half*)(smem + P_OFF);
    float* rs_sm = (float*)(smem + RS_OFF);

    const int tid  = threadIdx.x;
    const int lane = tid & 31;
    const int warp = tid >> 5;
    const int rg   = warp & 3;          // 32-row group
    const int ch   = warp >> 2;         // 32-col half
    const int blk  = blockIdx.x;        // 0..255
    const int b    = blk >> 5;
    const int i0   = (blk & 31) * BI;

    const int cx = tid & 15;            // 4 j-columns per thread
    const int ry = tid >> 4;            // 0..15

    if (tid == 0) {
        MBINIT(sb + BAR_OFF + 0, 1);
        MBINIT(sb + BAR_OFF + 8, 1);
    }
    __syncthreads();

    float acc[2][4][4];                 // [rt][nt][frag]
#pragma unroll
    for (int rt = 0; rt < 2; rt++)
#pragma unroll
        for (int nt = 0; nt < 4; nt++)
#pragma unroll
            for (int k = 0; k < 4; k++) acc[rt][nt][k] = 0.f;

    // per-row P1/Q1 (rows ps*16 + ry) + fp32 rowsum accumulators
    float P1f[8], Q1f[8], rsl[8];
    {
        const float2* pq1b = pq1_g + b * NN + i0;
#pragma unroll
        for (int ps = 0; ps < 8; ps++) {
            float2 pq = __ldg(&pq1b[ps * 16 + ry]);
            P1f[ps] = pq.x; Q1f[ps] = pq.y;
            rsl[ps] = 0.f;
        }
    }

    const float2* pq2b = pq2_g + b * NN;
    const char*   hgb  = (const char*)h_fp16 + (size_t)b * NN * (FO * 2);  // swizzled tiles

    // ldmatrix lane addressing: A row-tiles rt0/rt1 at rg*32 and rg*32+16
    const uint32_t a_addr0 = sb + P_OFF
        + (uint32_t)(((rg * 32 + (lane & 15)) * PPITCH + (lane >> 4) * 8) * 2);
    const uint32_t a_addr1 = a_addr0 + (uint32_t)(16 * PPITCH * 2);
    const uint32_t b_base = sb + H_OFF
        + (uint32_t)((lane & 15) * 128)
        + (uint32_t)(((uint32_t)(ch * 64) | (((uint32_t)lane >> 4) << 4)) ^ (((uint32_t)lane & 7u) << 4));

    auto issue = [&](int u) {
        const int s = u & 1;
        const uint32_t bar = sb + BAR_OFF + s * 8;
        MBEXP(bar, ASTAGE_B + HSTAGE_B);
        tma3d(sb + ADJ_OFF + s * ASTAGE_B, &tm_adj, u * BJ, i0, b, bar);
        bulk_g2s(sb + H_OFF + s * HSTAGE_B, hgb + (size_t)u * HSTAGE_B, HSTAGE_B, bar);
    };

    if (tid == 0) issue(0);

    for (int t = 0; t < NT; t++) {
        const int s = t & 1;

        // Keep TWO tiles in flight: request t+1 BEFORE blocking on t.
        // Stage (t+1)&1 was last read by MMA(t-1), which completed before the
        // end-of-iteration __syncthreads of iter t-1.
        if (tid == 0 && t + 1 < NT) issue(t + 1);

        MBWAIT(sb + BAR_OFF + s * 8, (t >> 1) & 1);  // tile t resident

        // ---- p tile (128 x 64) -> p_sm; fp32 rowsum in regs ----
        const uint32_t astage = sb + ADJ_OFF + s * ASTAGE_B;
        float4 pa = *(const float4*)(pq2b + t * BJ + cx * 4);
        float4 pb = *(const float4*)(pq2b + t * BJ + cx * 4 + 2);
#pragma unroll
        for (int ps = 0; ps < 8; ps++) {
            int row = ps * 16 + ry;
            int4 av;
            asm volatile("ld.shared.v4.u32 {%0,%1,%2,%3}, [%4];"
                         : "=r"(av.x), "=r"(av.y), "=r"(av.z), "=r"(av.w)
                         : "r"(astage + (uint32_t)(row * 256 + cx * 16)));
            float p0 = av.x ? fmaxf(P1f[ps] * pa.x, Q1f[ps] * pa.y) : 0.f;
            float p1 = av.y ? fmaxf(P1f[ps] * pa.z, Q1f[ps] * pa.w) : 0.f;
            float p2 = av.z ? fmaxf(P1f[ps] * pb.x, Q1f[ps] * pb.y) : 0.f;
            float p3 = av.w ? fmaxf(P1f[ps] * pb.z, Q1f[ps] * pb.w) : 0.f;
            __half2 q01 = __floats2half2_rn(p0, p1);
            __half2 q23 = __floats2half2_rn(p2, p3);
            float2 lo = __half22float2(q01);
            float2 hi = __half22float2(q23);
            rsl[ps] += (lo.x + lo.y) + (hi.x + hi.y);
            uint2 pk;
            pk.x = reinterpret_cast<uint32_t&>(q01);
            pk.y = reinterpret_cast<uint32_t&>(q23);
            *reinterpret_cast<uint2*>(&p_sm[row * PPITCH + cx * 4]) = pk;
        }

        __syncthreads();                             // B2: p_sm + h ready

        // ---- MMA: acc += p @ h; B fragments shared across 2 row-tiles ----
        const uint32_t hb = b_base + (uint32_t)(s * HSTAGE_B);
#pragma unroll
        for (int ks = 0; ks < 4; ks++) {
            uint32_t a0, a1, a2, a3, a4, a5, a6, a7;
            ldsm4(a0, a1, a2, a3, a_addr0 + ks * 32);
            ldsm4(a4, a5, a6, a7, a_addr1 + ks * 32);
            uint32_t baddr = hb + (uint32_t)(ks * 2048);
            uint32_t b0, b1, b2, b3;
            ldsm4t(b0, b1, b2, b3, baddr);
            mma16816(acc[0][0], a0, a1, a2, a3, b0, b1);
            mma16816(acc[0][1], a0, a1, a2, a3, b2, b3);
            mma16816(acc[1][0], a4, a5, a6, a7, b0, b1);
            mma16816(acc[1][1], a4, a5, a6, a7, b2, b3);
            uint32_t c0, c1, c2, c3;
            ldsm4t(c0, c1, c2, c3, baddr ^ 32u);
            mma16816(acc[0][2], a0, a1, a2, a3, c0, c1);
            mma16816(acc[0][3], a0, a1, a2, a3, c2, c3);
            mma16816(acc[1][2], a4, a5, a6, a7, c0, c1);
            mma16816(acc[1][3], a4, a5, a6, a7, c2, c3);
        }

        __syncthreads();        // B1: all reads of p_sm + stage s done
    }

    // ---- epilogue: rowsums -> SMEM, divide, elu, store ----
#pragma unroll
    for (int ps = 0; ps < 8; ps++) {
        float v = rsl[ps];
#pragma unroll
        for (int m = 8; m >= 1; m >>= 1)
            v += __shfl_xor_sync(0xffffffffu, v, m);
        if (cx == 0) rs_sm[ps * 16 + ry] = v;
    }
    __syncthreads();

    float* ob = out + (size_t)b * NN * FO;
#pragma unroll
    for (int rt = 0; rt < 2; rt++) {
        const int r_loc = rg * 32 + rt * 16 + (lane >> 2);
        const float inv_lo = 1.f / rs_sm[r_loc];
        const float inv_hi = 1.f / rs_sm[r_loc + 8];
#pragma unroll
        for (int nt = 0; nt < 4; nt++) {
            int col = ch * 32 + nt * 8 + (lane & 3) * 2;
            float v0 = acc[rt][nt][0] * inv_lo;
            float v1 = acc[rt][nt][1] * inv_lo;
            float v2 = acc[rt][nt][2] * inv_hi;
            float v3 = acc[rt][nt][3] * inv_hi;
            v0 = v0 > 0.f ? v0 : expm1f(v0);
            v1 = v1 > 0.f ? v1 : expm1f(v1);
            v2 = v2 > 0.f ? v2 : expm1f(v2);
            v3 = v3 > 0.f ? v3 : expm1f(v3);
            *reinterpret_cast<float2*>(&ob[(size_t)(i0 + r_loc) * FO + col])     = make_float2(v0, v1);
            *reinterpret_cast<float2*>(&ob[(size_t)(i0 + r_loc + 8) * FO + col]) = make_float2(v2, v3);
        }
    }
}

// ---------------------------------------------------------------------------
extern "C" void kernel_launch(void* const* d_in, const int* in_sizes, int n_in,
                              void* d_out, int out_size)
{
    const float* inp = (const float*)d_in[0];
    const int*   adj = (const int*)d_in[1];
    const float* W   = (const float*)d_in[2];
    const float* a   = (const float*)d_in[3];
    float* out = (float*)d_out;

    cudaFuncSetAttribute(k_h, cudaFuncAttributeMaxDynamicSharedMemorySize, KH_SMEM);
    cudaFuncSetAttribute(k_attn, cudaFuncAttributeMaxDynamicSharedMemorySize, ATTN_SMEM);

    typedef CUresult (*EncodeFn)(CUtensorMap*, CUtensorMapDataType, cuuint32_t, void*,
                                 const cuuint64_t*, const cuuint64_t*, const cuuint32_t*,
                                 const cuuint32_t*, CUtensorMapInterleave, CUtensorMapSwizzle,
                                 CUtensorMapL2promotion, CUtensorMapFloatOOBfill);
    EncodeFn encode = nullptr;
    {
        void* fn = nullptr;
        cudaDriverEntryPointQueryResult q;
        cudaGetDriverEntryPointByVersion("cuTensorMapEncodeTiled", &fn, 12030,
                                         cudaEnableDefault, &q);
        encode = (EncodeFn)fn;
    }

    // adj: (x=j 4096, y=i 4096, z=b 8), box (64, 128, 1), no swizzle (256B rows)
    CUtensorMap tm_adj;
    {
        cuuint64_t dims[3]    = {(cuuint64_t)NN, (cuuint64_t)NN, (cuuint64_t)BB};
        cuuint64_t strides[2] = {(cuuint64_t)NN * 4, (cuuint64_t)NN * NN * 4};
        cuuint32_t box[3]     = {BJ, BI, 1};
        cuuint32_t estr[3]    = {1, 1, 1};
        encode(&tm_adj, CU_TENSOR_MAP_DATA_TYPE_UINT32, 3, (void*)adj,
               dims, strides, box, estr,
               CU_TENSOR_MAP_INTERLEAVE_NONE, CU_TENSOR_MAP_SWIZZLE_NONE,
               CU_TENSOR_MAP_L2_PROMOTION_L2_128B, CU_TENSOR_MAP_FLOAT_OOB_FILL_NONE);
    }

    k_h<<<BB * NN / 64, 256, KH_SMEM>>>(inp, W, a);
    k_pq<<<BB, 512>>>();
    k_attn<<<BB * (NN / BI), 256, ATTN_SMEM>>>(tm_adj, out);
}

// round 13
// speedup vs baseline: 1.0266x; 1.0266x over previous
#include <cuda_runtime.h>
#include <cuda_fp16.h>
#include <cuda.h>
#include <cstdint>

#define BB 8
#define NN 4096
#define FI 128
#define FO 64
#define BI 128
#define BJ 64
#define NT (NN / BJ)
#define PPITCH 72

// k_attn shared memory layout (dynamic):
//   adj: 2 stages x 32768B (128 rows x 256B; TMA box 64x128 ints)
//   h:   2 stages x 8192B  (SW128-swizzled tiles, 1D bulk)
//   p:   1 buffer 18432B (128 x 72 halves)
//   rs:  128 floats; 4 mbarriers (full0,full1,free0,free1)
#define ASTAGE_B 32768
#define HSTAGE_B 8192
#define ADJ_OFF  0
#define H_OFF    (2 * ASTAGE_B)             // 65536
#define P_OFF    (H_OFF + 2 * HSTAGE_B)     // 81920
#define RS_OFF   (P_OFF + BI * PPITCH * 2)  // 100352
#define BAR_OFF  (RS_OFF + BI * 4)          // 100864
#define ATTN_SMEM (BAR_OFF + 32)            // 100896

// Scratch (static __device__ — no allocation allowed)
// h_fp16: per batch, tile-major; within 64-row tile: row lr, byte col cb at
// lr*128 + (cb ^ ((lr&7)<<4))  (SW128 pre-swizzle).
__device__ __align__(1024) __half h_fp16[(size_t)BB * NN * FO];   // 4 MB
__device__ float  s1_g[BB * NN];
__device__ float  s2_g[BB * NN];
__device__ float2 pq1_g[BB * NN];                 // {P1, Q1} per (b,i)
__device__ float2 pq2_g[BB * NN];                 // {P2, Q2} per (b,j)

// ---------------------------------------------------------------------------
// Kernel A1: h = inp @ W (fp32, fp16 store swizzled), s1 = h@a1, s2 = h@a2
// ---------------------------------------------------------------------------
#define KH_IPITCH 132
#define KH_SMEM ((FI * FO + 64 * KH_IPITCH + 2 * FO) * 4)

__global__ __launch_bounds__(256) void k_h(const float* __restrict__ inp,
                                           const float* __restrict__ W,
                                           const float* __restrict__ a)
{
    extern __shared__ float sm_f[];
    float* W_sm   = sm_f;                       // 128*64
    float* inp_sm = sm_f + FI * FO;             // 64*132
    float* a_sm   = inp_sm + 64 * KH_IPITCH;    // 128

    const int tid = threadIdx.x;
    const int blk = blockIdx.x;                 // 0 .. BB*NN/64-1
    const int b   = blk / (NN / 64);
    const int i0  = (blk % (NN / 64)) * 64;

#pragma unroll
    for (int k = 0; k < 8; k++)
        ((float4*)W_sm)[tid + k * 256] = ((const float4*)W)[tid + k * 256];
    if (tid < 2 * FO) a_sm[tid] = a[tid];
    const float* inp_b = inp + ((size_t)b * NN + i0) * FI;
#pragma unroll
    for (int k = 0; k < 8; k++) {
        int c = tid + k * 256;
        int row = c >> 5, col = c & 31;
        *(float4*)(inp_sm + row * KH_IPITCH + col * 4) = ((const float4*)inp_b)[c];
    }
    __syncthreads();

    const int ox = tid & 15;
    const int rg = tid >> 4;
    const float4* Wv = (const float4*)W_sm;

    float4 acc[4];
#pragma unroll
    for (int k = 0; k < 4; k++) acc[k] = make_float4(0.f, 0.f, 0.f, 0.f);

#pragma unroll 4
    for (int f = 0; f < FI; f++) {
        float4 w = Wv[f * 16 + ox];
#pragma unroll
        for (int k = 0; k < 4; k++) {
            float x = inp_sm[(rg + 16 * k) * KH_IPITCH + f];
            acc[k].x += x * w.x; acc[k].y += x * w.y;
            acc[k].z += x * w.z; acc[k].w += x * w.w;
        }
    }

    char* tile_base = (char*)h_fp16 + ((size_t)b * NN + i0) * (FO * 2);

    const int o4 = ox * 4;
#pragma unroll
    for (int k = 0; k < 4; k++) {
        float s1p = acc[k].x * a_sm[o4] + acc[k].y * a_sm[o4 + 1]
                  + acc[k].z * a_sm[o4 + 2] + acc[k].w * a_sm[o4 + 3];
        float s2p = acc[k].x * a_sm[FO + o4] + acc[k].y * a_sm[FO + o4 + 1]
                  + acc[k].z * a_sm[FO + o4 + 2] + acc[k].w * a_sm[FO + o4 + 3];
#pragma unroll
        for (int m = 8; m >= 1; m >>= 1) {
            s1p += __shfl_xor_sync(0xffffffffu, s1p, m);
            s2p += __shfl_xor_sync(0xffffffffu, s2p, m);
        }
        const int lr = rg + 16 * k;
        const int grow = b * NN + i0 + lr;
        if (ox == 0) { s1_g[grow] = s1p; s2_g[grow] = s2p; }

        __half2 h01 = __floats2half2_rn(acc[k].x, acc[k].y);
        __half2 h23 = __floats2half2_rn(acc[k].z, acc[k].w);
        uint2 pk;
        pk.x = reinterpret_cast<uint32_t&>(h01);
        pk.y = reinterpret_cast<uint32_t&>(h23);
        uint32_t swz = (uint32_t)(lr * 128) + (((uint32_t)(ox * 8)) ^ (((uint32_t)lr & 7u) << 4));
        *reinterpret_cast<uint2*>(tile_base + swz) = pk;
    }
}

// ---------------------------------------------------------------------------
// Kernel A2: exp factor tables.  exp(lrelu(s1+s2) - M/L) = max(P1*P2, Q1*Q2)
// ---------------------------------------------------------------------------
__global__ void k_pq()
{
    const int b = blockIdx.x;
    const int tid = threadIdx.x;      // 512 threads
    __shared__ float red[16];

    const float* s2b = s2_g + b * NN;
    float mx = -1e30f;
    for (int j = tid; j < NN; j += 512) mx = fmaxf(mx, s2b[j]);
#pragma unroll
    for (int m = 16; m >= 1; m >>= 1)
        mx = fmaxf(mx, __shfl_xor_sync(0xffffffffu, mx, m));
    if ((tid & 31) == 0) red[tid >> 5] = mx;
    __syncthreads();
    if (tid == 0) {
        float v = red[0];
        for (int k = 1; k < 16; k++) v = fmaxf(v, red[k]);
        red[0] = v;
    }
    __syncthreads();

    const float L = 1.4426950408889634f;
    const float s2maxL = red[0] * L;
    for (int j = tid; j < NN; j += 512) {
        float sL = s2b[j] * L;
        pq2_g[b * NN + j] = make_float2(exp2f(sL), exp2f(0.2f * sL));
        float s1L = s1_g[b * NN + j] * L;
        float t = s1L + s2maxL;
        float M = fmaxf(t, 0.2f * t);
        pq1_g[b * NN + j] = make_float2(exp2f(s1L - M), exp2f(0.2f * s1L - M));
    }
}

// ---------------------------------------------------------------------------
// PTX helpers
// ---------------------------------------------------------------------------
__device__ __forceinline__ void ldsm4(uint32_t& r0, uint32_t& r1, uint32_t& r2, uint32_t& r3, uint32_t addr)
{
    asm volatile("ldmatrix.sync.aligned.m8n8.x4.shared.b16 {%0,%1,%2,%3}, [%4];"
                 : "=r"(r0), "=r"(r1), "=r"(r2), "=r"(r3) : "r"(addr));
}
__device__ __forceinline__ void ldsm4t(uint32_t& r0, uint32_t& r1, uint32_t& r2, uint32_t& r3, uint32_t addr)
{
    asm volatile("ldmatrix.sync.aligned.m8n8.x4.trans.shared.b16 {%0,%1,%2,%3}, [%4];"
                 : "=r"(r0), "=r"(r1), "=r"(r2), "=r"(r3) : "r"(addr));
}
__device__ __forceinline__ void mma16816(float* d, uint32_t a0, uint32_t a1, uint32_t a2, uint32_t a3,
                                         uint32_t b0, uint32_t b1)
{
    asm volatile("mma.sync.aligned.m16n8k16.row.col.f32.f16.f16.f32 "
                 "{%0,%1,%2,%3}, {%4,%5,%6,%7}, {%8,%9}, {%0,%1,%2,%3};"
                 : "+f"(d[0]), "+f"(d[1]), "+f"(d[2]), "+f"(d[3])
                 : "r"(a0), "r"(a1), "r"(a2), "r"(a3), "r"(b0), "r"(b1));
}
__device__ __forceinline__ void bulk_g2s(uint32_t dst, const void* src, uint32_t bytes, uint32_t bar)
{
    asm volatile("cp.async.bulk.shared::cluster.global.mbarrier::complete_tx::bytes "
                 "[%0], [%1], %2, [%3];"
                 :: "r"(dst), "l"(src), "r"(bytes), "r"(bar) : "memory");
}
__device__ __forceinline__ void tma3d(uint32_t dst, const CUtensorMap* map,
                                      int cx_, int cy_, int cz_, uint32_t bar)
{
    asm volatile("cp.async.bulk.tensor.3d.shared::cta.global.tile.mbarrier::complete_tx::bytes "
                 "[%0], [%1, {%2, %3, %4}], [%5];"
                 :: "r"(dst), "l"(map), "r"(cx_), "r"(cy_), "r"(cz_), "r"(bar) : "memory");
}
#define MBINIT(addr, cnt) \
    asm volatile("mbarrier.init.shared.b64 [%0], %1;" :: "r"(addr), "r"(cnt) : "memory")
#define MBARR(addr) \
    asm volatile("mbarrier.arrive.release.cta.shared.b64 _, [%0];" :: "r"(addr) : "memory")
#define MBEXP(addr, tx) \
    asm volatile("mbarrier.arrive.expect_tx.shared.b64 _, [%0], %1;" :: "r"(addr), "r"((uint32_t)(tx)) : "memory")
#define MBWAIT(addr, ph) do {                                                       \
    uint32_t _m = (addr); uint32_t _p = (ph); uint32_t _ok;                         \
    asm volatile("{\n\t.reg .pred p;\n\t"                                           \
        "mbarrier.try_wait.parity.acquire.cta.shared::cta.b64 p, [%1], %2;\n\t"     \
        "selp.b32 %0, 1, 0, p;\n\t}" : "=r"(_ok) : "r"(_m), "r"(_p) : "memory");    \
    if (!_ok) {                                                                     \
        asm volatile("{\n\t.reg .pred P1;\n\t"                                      \
            "WL_%=:\n\t"                                                            \
            "mbarrier.try_wait.parity.acquire.cta.shared::cta.b64 P1, [%0], %1, 0x989680;\n\t" \
            "@P1 bra.uni WD_%=;\n\t"                                                \
            "bra.uni WL_%=;\n\t"                                                    \
            "WD_%=:\n\t}" :: "r"(_m), "r"(_p) : "memory");                          \
    }                                                                               \
} while (0)
#define PAIRBAR(id) \
    asm volatile("bar.sync %0, 64;" :: "r"(id) : "memory")

// ---------------------------------------------------------------------------
// Kernel B: fused mask + softmax(no-rescale) + PV matmul + elu.
// 256 CTAs x 256 threads (8 warps), 2 CTAs/SM — SINGLE WAVE.
// Warp pairs {(rg,0),(rg,1)} are decoupled: each pair computes ITS OWN p rows
// (rg*32..+31) and syncs via a 64-thread named barrier; no CTA-wide syncs in
// the loop. Stage recycling: free[s] mbarrier (count 8, one arrive per warp
// after MMA); only tid0 waits it before issuing tile t+2.
// ---------------------------------------------------------------------------
__global__ __launch_bounds__(256, 2) void k_attn(
    const __grid_constant__ CUtensorMap tm_adj,
    float* __restrict__ out)
{
    extern __shared__ __align__(1024) unsigned char smem[];
    const uint32_t sb = (uint32_t)__cvta_generic_to_shared(smem);
    __half* p_sm = (__half*)(smem + P_OFF);
    float* rs_sm = (float*)(smem + RS_OFF);

    const int tid  = threadIdx.x;
    const int lane = tid & 31;
    const int warp = tid >> 5;
    const int rg   = warp & 3;          // 32-row group (pair id)
    const int ch   = warp >> 2;         // 32-col half = pair member
    const int blk  = blockIdx.x;        // 0..255
    const int b    = blk >> 5;
    const int i0   = (blk & 31) * BI;

    // pair-local thread coords: 64 threads cover 32 rows x 64 cols
    const int lane64 = ch * 32 + lane;      // 0..63 within pair
    const int cx  = lane64 & 15;            // 4 j-columns per thread
    const int ry2 = lane64 >> 4;            // 0..3 row-subgroup

    const uint32_t fullb = sb + BAR_OFF;        // full[0], full[1]
    const uint32_t freeb = sb + BAR_OFF + 16;   // free[0], free[1]

    if (tid == 0) {
        MBINIT(fullb + 0, 1);
        MBINIT(fullb + 8, 1);
        MBINIT(freeb + 0, 8);
        MBINIT(freeb + 8, 8);
    }
    __syncthreads();

    auto issue = [&](int u) {
        const int s = u & 1;
        const uint32_t bar = fullb + s * 8;
        MBEXP(bar, ASTAGE_B + HSTAGE_B);
        tma3d(sb + ADJ_OFF + s * ASTAGE_B, &tm_adj, u * BJ, i0, b, bar);
        bulk_g2s(sb + H_OFF + s * HSTAGE_B,
                 (const char*)h_fp16 + (size_t)b * NN * (FO * 2) + (size_t)u * HSTAGE_B,
                 HSTAGE_B, bar);
    };

    if (tid == 0) { issue(0); issue(1); }

    float acc[2][4][4];                 // [rt][nt][frag]
#pragma unroll
    for (int rt = 0; rt < 2; rt++)
#pragma unroll
        for (int nt = 0; nt < 4; nt++)
#pragma unroll
            for (int k = 0; k < 4; k++) acc[rt][nt][k] = 0.f;

    // per-row P1/Q1 for rows rg*32 + ps*4 + ry2, ps=0..7; + fp32 rowsums
    float P1f[8], Q1f[8], rsl[8];
    {
        const float2* pq1b = pq1_g + b * NN + i0 + rg * 32;
#pragma unroll
        for (int ps = 0; ps < 8; ps++) {
            float2 pq = __ldg(&pq1b[ps * 4 + ry2]);
            P1f[ps] = pq.x; Q1f[ps] = pq.y;
            rsl[ps] = 0.f;
        }
    }

    const float2* pq2b = pq2_g + b * NN;

    // ldmatrix lane addressing: A row-tiles rt0/rt1 at rg*32 and rg*32+16
    const uint32_t a_addr0 = sb + P_OFF
        + (uint32_t)(((rg * 32 + (lane & 15)) * PPITCH + (lane >> 4) * 8) * 2);
    const uint32_t a_addr1 = a_addr0 + (uint32_t)(16 * PPITCH * 2);
    const uint32_t b_base = sb + H_OFF
        + (uint32_t)((lane & 15) * 128)
        + (uint32_t)(((uint32_t)(ch * 64) | (((uint32_t)lane >> 4) << 4)) ^ (((uint32_t)lane & 7u) << 4));

    const int barid = rg + 1;           // named barriers 1..4 (0 = __syncthreads)

    for (int t = 0; t < NT; t++) {
        const int s = t & 1;
        const int ph = (t >> 1) & 1;
        MBWAIT(fullb + s * 8, ph);                   // tile t resident

        // ---- pair-local p rows (rg*32..+31) -> p_sm; fp32 rowsum in regs ----
        const uint32_t astage = sb + ADJ_OFF + s * ASTAGE_B;
        float4 pa = *(const float4*)(pq2b + t * BJ + cx * 4);
        float4 pb = *(const float4*)(pq2b + t * BJ + cx * 4 + 2);
#pragma unroll
        for (int ps = 0; ps < 8; ps++) {
            int row = rg * 32 + ps * 4 + ry2;
            int4 av;
            asm volatile("ld.shared.v4.u32 {%0,%1,%2,%3}, [%4];"
                         : "=r"(av.x), "=r"(av.y), "=r"(av.z), "=r"(av.w)
                         : "r"(astage + (uint32_t)(row * 256 + cx * 16)));
            float p0 = av.x ? fmaxf(P1f[ps] * pa.x, Q1f[ps] * pa.y) : 0.f;
            float p1 = av.y ? fmaxf(P1f[ps] * pa.z, Q1f[ps] * pa.w) : 0.f;
            float p2 = av.z ? fmaxf(P1f[ps] * pb.x, Q1f[ps] * pb.y) : 0.f;
            float p3 = av.w ? fmaxf(P1f[ps] * pb.z, Q1f[ps] * pb.w) : 0.f;
            __half2 q01 = __floats2half2_rn(p0, p1);
            __half2 q23 = __floats2half2_rn(p2, p3);
            float2 lo = __half22float2(q01);
            float2 hi = __half22float2(q23);
            rsl[ps] += (lo.x + lo.y) + (hi.x + hi.y);
            uint2 pk;
            pk.x = reinterpret_cast<uint32_t&>(q01);
            pk.y = reinterpret_cast<uint32_t&>(q23);
            *reinterpret_cast<uint2*>(&p_sm[row * PPITCH + cx * 4]) = pk;
        }

        PAIRBAR(barid);                              // pair's p rows visible

        // ---- MMA: acc += p @ h; B fragments shared across 2 row-tiles ----
        const uint32_t hb = b_base + (uint32_t)(s * HSTAGE_B);
#pragma unroll
        for (int ks = 0; ks < 4; ks++) {
            uint32_t a0, a1, a2, a3, a4, a5, a6, a7;
            ldsm4(a0, a1, a2, a3, a_addr0 + ks * 32);
            ldsm4(a4, a5, a6, a7, a_addr1 + ks * 32);
            uint32_t baddr = hb + (uint32_t)(ks * 2048);
            uint32_t b0, b1, b2, b3;
            ldsm4t(b0, b1, b2, b3, baddr);
            mma16816(acc[0][0], a0, a1, a2, a3, b0, b1);
            mma16816(acc[0][1], a0, a1, a2, a3, b2, b3);
            mma16816(acc[1][0], a4, a5, a6, a7, b0, b1);
            mma16816(acc[1][1], a4, a5, a6, a7, b2, b3);
            uint32_t c0, c1, c2, c3;
            ldsm4t(c0, c1, c2, c3, baddr ^ 32u);
            mma16816(acc[0][2], a0, a1, a2, a3, c0, c1);
            mma16816(acc[0][3], a0, a1, a2, a3, c2, c3);
            mma16816(acc[1][2], a4, a5, a6, a7, c0, c1);
            mma16816(acc[1][3], a4, a5, a6, a7, c2, c3);
        }

        // warp done reading adj[s] (p-compute) and h[s] (MMA): release stage
        if (lane == 0) MBARR(freeb + s * 8);

        // recycle stage s for tile t+2 (tid0 only; other pairs keep flowing)
        if (tid == 0 && t + 2 < NT) {
            MBWAIT(freeb + s * 8, ph);               // all 8 warps done with s
            issue(t + 2);
        }

        PAIRBAR(barid);                              // protect pair's p rows
    }

    // ---- epilogue: rowsums -> SMEM, divide, elu, store ----
#pragma unroll
    for (int ps = 0; ps < 8; ps++) {
        float v = rsl[ps];
#pragma unroll
        for (int m = 8; m >= 1; m >>= 1)
            v += __shfl_xor_sync(0xffffffffu, v, m);
        if (cx == 0) rs_sm[rg * 32 + ps * 4 + ry2] = v;
    }
    __syncthreads();

    float* ob = out + (size_t)b * NN * FO;
#pragma unroll
    for (int rt = 0; rt < 2; rt++) {
        const int r_loc = rg * 32 + rt * 16 + (lane >> 2);
        const float inv_lo = 1.f / rs_sm[r_loc];
        const float inv_hi = 1.f / rs_sm[r_loc + 8];
#pragma unroll
        for (int nt = 0; nt < 4; nt++) {
            int col = ch * 32 + nt * 8 + (lane & 3) * 2;
            float v0 = acc[rt][nt][0] * inv_lo;
            float v1 = acc[rt][nt][1] * inv_lo;
            float v2 = acc[rt][nt][2] * inv_hi;
            float v3 = acc[rt][nt][3] * inv_hi;
            v0 = v0 > 0.f ? v0 : expm1f(v0);
            v1 = v1 > 0.f ? v1 : expm1f(v1);
            v2 = v2 > 0.f ? v2 : expm1f(v2);
            v3 = v3 > 0.f ? v3 : expm1f(v3);
            *reinterpret_cast<float2*>(&ob[(size_t)(i0 + r_loc) * FO + col])     = make_float2(v0, v1);
            *reinterpret_cast<float2*>(&ob[(size_t)(i0 + r_loc + 8) * FO + col]) = make_float2(v2, v3);
        }
    }
}

// ---------------------------------------------------------------------------
extern "C" void kernel_launch(void* const* d_in, const int* in_sizes, int n_in,
                              void* d_out, int out_size)
{
    const float* inp = (const float*)d_in[0];
    const int*   adj = (const int*)d_in[1];
    const float* W   = (const float*)d_in[2];
    const float* a   = (const float*)d_in[3];
    float* out = (float*)d_out;

    cudaFuncSetAttribute(k_h, cudaFuncAttributeMaxDynamicSharedMemorySize, KH_SMEM);
    cudaFuncSetAttribute(k_attn, cudaFuncAttributeMaxDynamicSharedMemorySize, ATTN_SMEM);

    typedef CUresult (*EncodeFn)(CUtensorMap*, CUtensorMapDataType, cuuint32_t, void*,
                                 const cuuint64_t*, const cuuint64_t*, const cuuint32_t*,
                                 const cuuint32_t*, CUtensorMapInterleave, CUtensorMapSwizzle,
                                 CUtensorMapL2promotion, CUtensorMapFloatOOBfill);
    EncodeFn encode = nullptr;
    {
        void* fn = nullptr;
        cudaDriverEntryPointQueryResult q;
        cudaGetDriverEntryPointByVersion("cuTensorMapEncodeTiled", &fn, 12030,
                                         cudaEnableDefault, &q);
        encode = (EncodeFn)fn;
    }

    // adj: (x=j 4096, y=i 4096, z=b 8), box (64, 128, 1), no swizzle (256B rows)
    CUtensorMap tm_adj;
    {
        cuuint64_t dims[3]    = {(cuuint64_t)NN, (cuuint64_t)NN, (cuuint64_t)BB};
        cuuint64_t strides[2] = {(cuuint64_t)NN * 4, (cuuint64_t)NN * NN * 4};
        cuuint32_t box[3]     = {BJ, BI, 1};
        cuuint32_t estr[3]    = {1, 1, 1};
        encode(&tm_adj, CU_TENSOR_MAP_DATA_TYPE_UINT32, 3, (void*)adj,
               dims, strides, box, estr,
               CU_TENSOR_MAP_INTERLEAVE_NONE, CU_TENSOR_MAP_SWIZZLE_NONE,
               CU_TENSOR_MAP_L2_PROMOTION_L2_128B, CU_TENSOR_MAP_FLOAT_OOB_FILL_NONE);
    }

    k_h<<<BB * NN / 64, 256, KH_SMEM>>>(inp, W, a);
    k_pq<<<BB, 512>>>();
    k_attn<<<BB * (NN / BI), 256, ATTN_SMEM>>>(tm_adj, out);
}